// round 2
// baseline (speedup 1.0000x reference)
#include <cuda_runtime.h>

// ---------------------------------------------------------------------------
// CombinedGoalObsNetwork — CSR-gather formulation.
//   build CSR(dst) for both graphs -> warp-per-node gather-reduce (no atomics
//   on feature data) -> fused 2-layer MLPs with 4 threads/row.
// ---------------------------------------------------------------------------

#define F64 64
#define NTASK  32768
#define NACT   32768
#define EST_MAX 2100000
#define ETA_MAX 1100000

// Scratch (__device__ globals; allocation-free rule)
__device__ __align__(16) float g_h_task[NTASK * F64];
__device__ __align__(16) float g_x1    [NTASK * F64];
__device__ __align__(16) float g_h2    [NACT  * F64];

__device__ int g_deg_st[NTASK];
__device__ int g_off_st[NTASK + 1];
__device__ int g_cur_st[NTASK];
__device__ int g_deg_ta[NACT];
__device__ int g_off_ta[NACT + 1];
__device__ int g_cur_ta[NACT];

__device__ __align__(16) float4 g_rec_st[EST_MAX]; // {src(bits), ax, ay, pad}
__device__ int    g_rec_ta[ETA_MAX];               // src

// ---------------------------------------------------------------------------
// Histogram of destination degrees for both graphs.
// ---------------------------------------------------------------------------
__global__ void hist_kernel(const int* __restrict__ dst_st, int E_st,
                            const int* __restrict__ dst_ta, int E_ta)
{
    int tid = blockIdx.x * blockDim.x + threadIdx.x;
    int tot = gridDim.x * blockDim.x;
    for (int e = tid; e < E_st; e += tot) atomicAdd(&g_deg_st[__ldg(dst_st + e)], 1);
    for (int e = tid; e < E_ta; e += tot) atomicAdd(&g_deg_ta[__ldg(dst_ta + e)], 1);
}

// ---------------------------------------------------------------------------
// Exclusive scan of 32768 counters, one block of 1024 threads (32 per thread).
// ---------------------------------------------------------------------------
__global__ void scan_kernel(const int* __restrict__ deg,
                            int* __restrict__ off,
                            int* __restrict__ cur, int n)
{
    __shared__ int part[1024];
    const int t = threadIdx.x;
    const int per = n >> 10;           // n / 1024
    const int base = t * per;
    int s = 0;
    for (int i = 0; i < per; i++) s += deg[base + i];
    part[t] = s;
    __syncthreads();
    for (int d = 1; d < 1024; d <<= 1) {
        int v = (t >= d) ? part[t - d] : 0;
        __syncthreads();
        part[t] += v;
        __syncthreads();
    }
    int run = t ? part[t - 1] : 0;
    for (int i = 0; i < per; i++) {
        off[base + i] = run;
        cur[base + i] = run;
        run += deg[base + i];
    }
    if (t == 1023) off[n] = run;
}

// ---------------------------------------------------------------------------
// Scatter edge records into CSR slots (position via atomic cursor).
// ---------------------------------------------------------------------------
__global__ void scatter_st_kernel(const int* __restrict__ src,
                                  const int* __restrict__ dst,
                                  const float* __restrict__ ea, int E)
{
    int tid = blockIdx.x * blockDim.x + threadIdx.x;
    int tot = gridDim.x * blockDim.x;
    for (int e = tid; e < E; e += tot) {
        const int d = __ldg(dst + e);
        const int s = __ldg(src + e);
        const float2 a = __ldg((const float2*)ea + e);
        const int pos = atomicAdd(&g_cur_st[d], 1);
        g_rec_st[pos] = make_float4(__int_as_float(s), a.x, a.y, 0.f);
    }
}

__global__ void scatter_ta_kernel(const int* __restrict__ src,
                                  const int* __restrict__ dst, int E)
{
    int tid = blockIdx.x * blockDim.x + threadIdx.x;
    int tot = gridDim.x * blockDim.x;
    for (int e = tid; e < E; e += tot) {
        const int d = __ldg(dst + e);
        const int s = __ldg(src + e);
        const int pos = atomicAdd(&g_cur_ta[d], 1);
        g_rec_ta[pos] = s;
    }
}

// ---------------------------------------------------------------------------
// GINE aggregation: warp per task node. lane owns 2 features (float2).
//   h_task[row] = x_task[row] + sum_e relu(x_state[src_e] + ax*We0 + ay*We1 + be)
// ---------------------------------------------------------------------------
__global__ void agg_gine_kernel(const float* __restrict__ x_state,
                                const float* __restrict__ x_task,
                                const float* __restrict__ We,
                                const float* __restrict__ be, int n)
{
    const int gw = (blockIdx.x * blockDim.x + threadIdx.x) >> 5;
    if (gw >= n) return;
    const int lane = threadIdx.x & 31;

    const float2 w0 = __ldg((const float2*)We + lane);
    const float2 w1 = __ldg((const float2*)(We + F64) + lane);
    const float2 bb = __ldg((const float2*)be + lane);

    float2 acc = __ldg((const float2*)(x_task + (size_t)gw * F64) + lane);

    const int beg = g_off_st[gw];
    const int end = g_off_st[gw + 1];

    #pragma unroll 4
    for (int p = beg; p < end; p++) {
        const float4 r = __ldg(&g_rec_st[p]);
        const int s = __float_as_int(r.x);
        const float2 x = __ldg((const float2*)(x_state + (size_t)s * F64) + lane);
        acc.x += fmaxf(fmaf(r.y, w0.x, fmaf(r.z, w1.x, x.x + bb.x)), 0.f);
        acc.y += fmaxf(fmaf(r.y, w0.y, fmaf(r.z, w1.y, x.y + bb.y)), 0.f);
    }
    ((float2*)(g_h_task + (size_t)gw * F64))[lane] = acc;
}

// ---------------------------------------------------------------------------
// GIN aggregation: warp per actor node.
//   h2[row] = x_actor[row] + sum_e x1[src_e]
// ---------------------------------------------------------------------------
__global__ void agg_gin_kernel(const float* __restrict__ x_actor, int n)
{
    const int gw = (blockIdx.x * blockDim.x + threadIdx.x) >> 5;
    if (gw >= n) return;
    const int lane = threadIdx.x & 31;

    float2 acc = __ldg((const float2*)(x_actor + (size_t)gw * F64) + lane);

    const int beg = g_off_ta[gw];
    const int end = g_off_ta[gw + 1];

    #pragma unroll 4
    for (int p = beg; p < end; p++) {
        const int s = __ldg(&g_rec_ta[p]);
        const float2 x = *((const float2*)(g_x1 + (size_t)s * F64) + lane);
        acc.x += x.x;
        acc.y += x.y;
    }
    ((float2*)(g_h2 + (size_t)gw * F64))[lane] = acc;
}

// ---------------------------------------------------------------------------
// Fused 2-layer MLP: out = relu(in @ Wa + ba) @ Wb + bb
// 4 threads per row; thread q computes hidden[q*16..] then, via quad shfl
// exchange, output cols [q*16..q*16+16).
// ---------------------------------------------------------------------------
__global__ void mlp2_kernel(const float* __restrict__ in,
                            const float* __restrict__ Wa,
                            const float* __restrict__ ba,
                            const float* __restrict__ Wb,
                            const float* __restrict__ bb,
                            float* __restrict__ out, int n)
{
    __shared__ float sA[F64 * F64];
    __shared__ float sB[F64 * F64];
    __shared__ float sba[F64];
    __shared__ float sbb[F64];
    for (int i = threadIdx.x; i < F64 * F64; i += blockDim.x) { sA[i] = Wa[i]; sB[i] = Wb[i]; }
    if (threadIdx.x < F64) { sba[threadIdx.x] = ba[threadIdx.x]; sbb[threadIdx.x] = bb[threadIdx.x]; }
    __syncthreads();

    const int tid  = blockIdx.x * blockDim.x + threadIdx.x;
    int row = tid >> 2;
    const int q    = tid & 3;
    const int lane = threadIdx.x & 31;
    const bool valid = (row < n);
    if (!valid) row = n - 1;

    const float4* xp = (const float4*)(in + (size_t)row * F64);

    // layer 1: h[j] for cols q*16+j
    float h[16];
    #pragma unroll
    for (int j = 0; j < 16; j++) h[j] = sba[q * 16 + j];

    #pragma unroll
    for (int k4 = 0; k4 < 16; k4++) {
        const float4 xv = __ldg(xp + k4);
        #pragma unroll
        for (int kk = 0; kk < 4; kk++) {
            const float xk = (kk == 0) ? xv.x : (kk == 1) ? xv.y : (kk == 2) ? xv.z : xv.w;
            const float* wr = &sA[(k4 * 4 + kk) * F64 + q * 16];
            #pragma unroll
            for (int j4 = 0; j4 < 4; j4++) {
                const float4 w = *(const float4*)(wr + j4 * 4);
                h[4*j4+0] = fmaf(xk, w.x, h[4*j4+0]);
                h[4*j4+1] = fmaf(xk, w.y, h[4*j4+1]);
                h[4*j4+2] = fmaf(xk, w.z, h[4*j4+2]);
                h[4*j4+3] = fmaf(xk, w.w, h[4*j4+3]);
            }
        }
    }
    #pragma unroll
    for (int j = 0; j < 16; j++) h[j] = fmaxf(h[j], 0.f);

    // layer 2 via quad shfl exchange
    float o[16];
    #pragma unroll
    for (int j = 0; j < 16; j++) o[j] = sbb[q * 16 + j];

    const int qbase = lane & ~3;
    #pragma unroll
    for (int c = 0; c < 4; c++) {
        #pragma unroll
        for (int j2 = 0; j2 < 16; j2++) {
            const float hv = __shfl_sync(0xffffffffu, h[j2], qbase | c, 32);
            const float* wr = &sB[(c * 16 + j2) * F64 + q * 16];
            #pragma unroll
            for (int j4 = 0; j4 < 4; j4++) {
                const float4 w = *(const float4*)(wr + j4 * 4);
                o[4*j4+0] = fmaf(hv, w.x, o[4*j4+0]);
                o[4*j4+1] = fmaf(hv, w.y, o[4*j4+1]);
                o[4*j4+2] = fmaf(hv, w.z, o[4*j4+2]);
                o[4*j4+3] = fmaf(hv, w.w, o[4*j4+3]);
            }
        }
    }

    if (valid) {
        float4* op = (float4*)(out + (size_t)row * F64) + q * 4;
        #pragma unroll
        for (int i = 0; i < 4; i++)
            op[i] = make_float4(o[4*i+0], o[4*i+1], o[4*i+2], o[4*i+3]);
    }
}

// ---------------------------------------------------------------------------
// Fused MLP2 + head: out[row] = relu(in @ W2a + b2a) @ W2b + b2b  (scalar)
// 4 threads/row: thread q does hidden[q*16..], partial dot, quad-reduce.
// ---------------------------------------------------------------------------
__global__ void mlp_head_kernel(const float* __restrict__ in,
                                const float* __restrict__ Wa,
                                const float* __restrict__ ba,
                                const float* __restrict__ wv,
                                const float* __restrict__ bv,
                                float* __restrict__ out, int n)
{
    __shared__ float sA[F64 * F64];
    __shared__ float sba[F64];
    __shared__ float sw[F64];
    for (int i = threadIdx.x; i < F64 * F64; i += blockDim.x) sA[i] = Wa[i];
    if (threadIdx.x < F64) { sba[threadIdx.x] = ba[threadIdx.x]; sw[threadIdx.x] = wv[threadIdx.x]; }
    __syncthreads();

    const int tid = blockIdx.x * blockDim.x + threadIdx.x;
    int row = tid >> 2;
    const int q = tid & 3;
    const bool valid = (row < n);
    if (!valid) row = n - 1;

    const float4* xp = (const float4*)(in + (size_t)row * F64);

    float h[16];
    #pragma unroll
    for (int j = 0; j < 16; j++) h[j] = sba[q * 16 + j];

    #pragma unroll
    for (int k4 = 0; k4 < 16; k4++) {
        const float4 xv = __ldg(xp + k4);
        #pragma unroll
        for (int kk = 0; kk < 4; kk++) {
            const float xk = (kk == 0) ? xv.x : (kk == 1) ? xv.y : (kk == 2) ? xv.z : xv.w;
            const float* wr = &sA[(k4 * 4 + kk) * F64 + q * 16];
            #pragma unroll
            for (int j4 = 0; j4 < 4; j4++) {
                const float4 w = *(const float4*)(wr + j4 * 4);
                h[4*j4+0] = fmaf(xk, w.x, h[4*j4+0]);
                h[4*j4+1] = fmaf(xk, w.y, h[4*j4+1]);
                h[4*j4+2] = fmaf(xk, w.z, h[4*j4+2]);
                h[4*j4+3] = fmaf(xk, w.w, h[4*j4+3]);
            }
        }
    }

    float s = 0.f;
    #pragma unroll
    for (int j = 0; j < 16; j++) s = fmaf(fmaxf(h[j], 0.f), sw[q * 16 + j], s);

    s += __shfl_xor_sync(0xffffffffu, s, 1, 32);
    s += __shfl_xor_sync(0xffffffffu, s, 2, 32);

    if (valid && q == 0) out[row] = s + __ldg(bv);
}

// ---------------------------------------------------------------------------
static inline int imin(int a, int b) { return a < b ? a : b; }

extern "C" void kernel_launch(void* const* d_in, const int* in_sizes, int n_in,
                              void* d_out, int out_size)
{
    const float* x_state   = (const float*)d_in[0];
    const float* x_task    = (const float*)d_in[1];
    const float* x_actor   = (const float*)d_in[2];
    const float* edge_attr = (const float*)d_in[3];
    const float* We  = (const float*)d_in[4];
    const float* be  = (const float*)d_in[5];
    const float* W1a = (const float*)d_in[6];
    const float* b1a = (const float*)d_in[7];
    const float* W1b = (const float*)d_in[8];
    const float* b1b = (const float*)d_in[9];
    const float* W2a = (const float*)d_in[10];
    const float* b2a = (const float*)d_in[11];
    const float* W2b = (const float*)d_in[12];
    const float* b2b = (const float*)d_in[13];
    const int* src_st = (const int*)d_in[14];
    const int* dst_st = (const int*)d_in[15];
    const int* src_ta = (const int*)d_in[16];
    const int* dst_ta = (const int*)d_in[17];

    const int n_task  = in_sizes[1] / F64;
    const int n_actor = in_sizes[2] / F64;
    const int E_st = in_sizes[14];
    const int E_ta = in_sizes[16];

    float *p_h_task, *p_x1, *p_h2;
    cudaGetSymbolAddress((void**)&p_h_task, g_h_task);
    cudaGetSymbolAddress((void**)&p_x1,     g_x1);
    cudaGetSymbolAddress((void**)&p_h2,     g_h2);
    int *p_deg_st, *p_deg_ta;
    cudaGetSymbolAddress((void**)&p_deg_st, g_deg_st);
    cudaGetSymbolAddress((void**)&p_deg_ta, g_deg_ta);

    // 1) degree histograms
    cudaMemsetAsync(p_deg_st, 0, n_task * sizeof(int));
    cudaMemsetAsync(p_deg_ta, 0, n_actor * sizeof(int));
    hist_kernel<<<1024, 256>>>(dst_st, E_st, dst_ta, E_ta);

    // 2) offsets
    {
        int *deg_st, *off_st, *cur_st, *deg_ta, *off_ta, *cur_ta;
        cudaGetSymbolAddress((void**)&deg_st, g_deg_st);
        cudaGetSymbolAddress((void**)&off_st, g_off_st);
        cudaGetSymbolAddress((void**)&cur_st, g_cur_st);
        cudaGetSymbolAddress((void**)&deg_ta, g_deg_ta);
        cudaGetSymbolAddress((void**)&off_ta, g_off_ta);
        cudaGetSymbolAddress((void**)&cur_ta, g_cur_ta);
        scan_kernel<<<1, 1024>>>(deg_st, off_st, cur_st, n_task);
        scan_kernel<<<1, 1024>>>(deg_ta, off_ta, cur_ta, n_actor);
    }

    // 3) edge record scatter
    scatter_st_kernel<<<2048, 256>>>(src_st, dst_st, edge_attr, E_st);
    scatter_ta_kernel<<<1024, 256>>>(src_ta, dst_ta, E_ta);

    // 4) GINE gather-reduce (+ residual) -> h_task
    agg_gine_kernel<<<(n_task * 32 + 255) / 256, 256>>>(x_state, x_task, We, be, n_task);

    // 5) task MLP (fused 2-layer) -> x1
    mlp2_kernel<<<(n_task * 4 + 255) / 256, 256>>>(p_h_task, W1a, b1a, W1b, b1b, p_x1, n_task);

    // 6) GIN gather-reduce (+ residual) -> h2
    agg_gin_kernel<<<(n_actor * 32 + 255) / 256, 256>>>(x_actor, n_actor);

    // 7) actor MLP + head -> logits
    mlp_head_kernel<<<(n_actor * 4 + 255) / 256, 256>>>(p_h2, W2a, b2a, W2b, b2b,
                                                        (float*)d_out, n_actor);
}

// round 3
// speedup vs baseline: 1.7107x; 1.7107x over previous
#include <cuda_runtime.h>

// ---------------------------------------------------------------------------
// CombinedGoalObsNetwork — hybrid: R1 atomic edge kernels + fused 2-layer MLPs.
// ---------------------------------------------------------------------------

#define F64 64
#define NTASK_MAX  32768
#define NACT_MAX   32768

__device__ __align__(16) float g_h_task[NTASK_MAX * F64];
__device__ __align__(16) float g_x1    [NTASK_MAX * F64];
__device__ __align__(16) float g_h2    [NACT_MAX  * F64];

// ---------------------------------------------------------------------------
// Init: h_task = x_task ; h2 = x_actor (scatter-adds land on the residual)
// ---------------------------------------------------------------------------
__global__ void init_kernel(const float* __restrict__ x_task,
                            const float* __restrict__ x_actor,
                            int n_task, int n_actor)
{
    int tot = gridDim.x * blockDim.x;
    int tid = blockIdx.x * blockDim.x + threadIdx.x;
    int nt4 = n_task * (F64 / 4);
    int na4 = n_actor * (F64 / 4);
    const float4* xt = (const float4*)x_task;
    const float4* xa = (const float4*)x_actor;
    float4* ht = (float4*)g_h_task;
    float4* h2 = (float4*)g_h2;
    for (int i = tid; i < nt4; i += tot) ht[i] = xt[i];
    for (int i = tid; i < na4; i += tot) h2[i] = xa[i];
}

__device__ __forceinline__ void red_add_v4(float* p, float4 v)
{
    asm volatile("red.global.add.v4.f32 [%0], {%1,%2,%3,%4};"
                 :: "l"(p), "f"(v.x), "f"(v.y), "f"(v.z), "f"(v.w)
                 : "memory");
}

// ---------------------------------------------------------------------------
// GINEConv edge kernel: 16 lanes/edge, float4 per lane.
// ---------------------------------------------------------------------------
__global__ void edge_gine_kernel(const float* __restrict__ x_state,
                                 const float* __restrict__ edge_attr,
                                 const float* __restrict__ We,
                                 const float* __restrict__ be,
                                 const int*   __restrict__ src,
                                 const int*   __restrict__ dst,
                                 int E)
{
    const int lane = threadIdx.x & 15;
    const float4 w0 = __ldg((const float4*)We + lane);
    const float4 w1 = __ldg((const float4*)(We + F64) + lane);
    const float4 bb = __ldg((const float4*)be + lane);

    int g  = (blockIdx.x * blockDim.x + threadIdx.x) >> 4;
    int gs = (gridDim.x * blockDim.x) >> 4;

    #pragma unroll 2
    for (int e = g; e < E; e += gs) {
        const int s = __ldg(src + e);
        const int d = __ldg(dst + e);
        const float2 a = __ldg((const float2*)edge_attr + e);
        const float4 x = __ldg((const float4*)(x_state + (size_t)s * F64) + lane);
        float4 v;
        v.x = fmaxf(fmaf(a.x, w0.x, fmaf(a.y, w1.x, x.x + bb.x)), 0.f);
        v.y = fmaxf(fmaf(a.x, w0.y, fmaf(a.y, w1.y, x.y + bb.y)), 0.f);
        v.z = fmaxf(fmaf(a.x, w0.z, fmaf(a.y, w1.z, x.z + bb.z)), 0.f);
        v.w = fmaxf(fmaf(a.x, w0.w, fmaf(a.y, w1.w, x.w + bb.w)), 0.f);
        red_add_v4(g_h_task + (size_t)d * F64 + lane * 4, v);
    }
}

// ---------------------------------------------------------------------------
// GINConv edge kernel: gather x1 row, scatter-add.
// ---------------------------------------------------------------------------
__global__ void edge_gin_kernel(const int* __restrict__ src,
                                const int* __restrict__ dst,
                                int E)
{
    const int lane = threadIdx.x & 15;
    int g  = (blockIdx.x * blockDim.x + threadIdx.x) >> 4;
    int gs = (gridDim.x * blockDim.x) >> 4;

    #pragma unroll 2
    for (int e = g; e < E; e += gs) {
        const int s = __ldg(src + e);
        const int d = __ldg(dst + e);
        const float4 v = *((const float4*)(g_x1 + (size_t)s * F64) + lane);
        red_add_v4(g_h2 + (size_t)d * F64 + lane * 4, v);
    }
}

// ---------------------------------------------------------------------------
// Fused 2-layer MLP: out = relu(in @ Wa + ba) @ Wb + bb
// 4 threads/row; thread q computes hidden[q*16..], quad shfl exchange for L2.
// ---------------------------------------------------------------------------
__global__ void mlp2_kernel(const float* __restrict__ in,
                            const float* __restrict__ Wa,
                            const float* __restrict__ ba,
                            const float* __restrict__ Wb,
                            const float* __restrict__ bb,
                            float* __restrict__ out, int n)
{
    __shared__ float sA[F64 * F64];
    __shared__ float sB[F64 * F64];
    __shared__ float sba[F64];
    __shared__ float sbb[F64];
    for (int i = threadIdx.x; i < F64 * F64; i += blockDim.x) { sA[i] = Wa[i]; sB[i] = Wb[i]; }
    if (threadIdx.x < F64) { sba[threadIdx.x] = ba[threadIdx.x]; sbb[threadIdx.x] = bb[threadIdx.x]; }
    __syncthreads();

    const int tid  = blockIdx.x * blockDim.x + threadIdx.x;
    int row = tid >> 2;
    const int q    = tid & 3;
    const int lane = threadIdx.x & 31;
    const bool valid = (row < n);
    if (!valid) row = n - 1;

    const float4* xp = (const float4*)(in + (size_t)row * F64);

    float h[16];
    #pragma unroll
    for (int j = 0; j < 16; j++) h[j] = sba[q * 16 + j];

    #pragma unroll
    for (int k4 = 0; k4 < 16; k4++) {
        const float4 xv = __ldg(xp + k4);
        #pragma unroll
        for (int kk = 0; kk < 4; kk++) {
            const float xk = (kk == 0) ? xv.x : (kk == 1) ? xv.y : (kk == 2) ? xv.z : xv.w;
            const float* wr = &sA[(k4 * 4 + kk) * F64 + q * 16];
            #pragma unroll
            for (int j4 = 0; j4 < 4; j4++) {
                const float4 w = *(const float4*)(wr + j4 * 4);
                h[4*j4+0] = fmaf(xk, w.x, h[4*j4+0]);
                h[4*j4+1] = fmaf(xk, w.y, h[4*j4+1]);
                h[4*j4+2] = fmaf(xk, w.z, h[4*j4+2]);
                h[4*j4+3] = fmaf(xk, w.w, h[4*j4+3]);
            }
        }
    }
    #pragma unroll
    for (int j = 0; j < 16; j++) h[j] = fmaxf(h[j], 0.f);

    float o[16];
    #pragma unroll
    for (int j = 0; j < 16; j++) o[j] = sbb[q * 16 + j];

    const int qbase = lane & ~3;
    #pragma unroll
    for (int c = 0; c < 4; c++) {
        #pragma unroll
        for (int j2 = 0; j2 < 16; j2++) {
            const float hv = __shfl_sync(0xffffffffu, h[j2], qbase | c, 32);
            const float* wr = &sB[(c * 16 + j2) * F64 + q * 16];
            #pragma unroll
            for (int j4 = 0; j4 < 4; j4++) {
                const float4 w = *(const float4*)(wr + j4 * 4);
                o[4*j4+0] = fmaf(hv, w.x, o[4*j4+0]);
                o[4*j4+1] = fmaf(hv, w.y, o[4*j4+1]);
                o[4*j4+2] = fmaf(hv, w.z, o[4*j4+2]);
                o[4*j4+3] = fmaf(hv, w.w, o[4*j4+3]);
            }
        }
    }

    if (valid) {
        float4* op = (float4*)(out + (size_t)row * F64) + q * 4;
        #pragma unroll
        for (int i = 0; i < 4; i++)
            op[i] = make_float4(o[4*i+0], o[4*i+1], o[4*i+2], o[4*i+3]);
    }
}

// ---------------------------------------------------------------------------
// Fused MLP + head: out[row] = relu(in @ W2a + b2a) @ W2b + b2b (64->1)
// ---------------------------------------------------------------------------
__global__ void mlp_head_kernel(const float* __restrict__ in,
                                const float* __restrict__ Wa,
                                const float* __restrict__ ba,
                                const float* __restrict__ wv,
                                const float* __restrict__ bv,
                                float* __restrict__ out, int n)
{
    __shared__ float sA[F64 * F64];
    __shared__ float sba[F64];
    __shared__ float sw[F64];
    for (int i = threadIdx.x; i < F64 * F64; i += blockDim.x) sA[i] = Wa[i];
    if (threadIdx.x < F64) { sba[threadIdx.x] = ba[threadIdx.x]; sw[threadIdx.x] = wv[threadIdx.x]; }
    __syncthreads();

    const int tid = blockIdx.x * blockDim.x + threadIdx.x;
    int row = tid >> 2;
    const int q = tid & 3;
    const bool valid = (row < n);
    if (!valid) row = n - 1;

    const float4* xp = (const float4*)(in + (size_t)row * F64);

    float h[16];
    #pragma unroll
    for (int j = 0; j < 16; j++) h[j] = sba[q * 16 + j];

    #pragma unroll
    for (int k4 = 0; k4 < 16; k4++) {
        const float4 xv = __ldg(xp + k4);
        #pragma unroll
        for (int kk = 0; kk < 4; kk++) {
            const float xk = (kk == 0) ? xv.x : (kk == 1) ? xv.y : (kk == 2) ? xv.z : xv.w;
            const float* wr = &sA[(k4 * 4 + kk) * F64 + q * 16];
            #pragma unroll
            for (int j4 = 0; j4 < 4; j4++) {
                const float4 w = *(const float4*)(wr + j4 * 4);
                h[4*j4+0] = fmaf(xk, w.x, h[4*j4+0]);
                h[4*j4+1] = fmaf(xk, w.y, h[4*j4+1]);
                h[4*j4+2] = fmaf(xk, w.z, h[4*j4+2]);
                h[4*j4+3] = fmaf(xk, w.w, h[4*j4+3]);
            }
        }
    }

    float s = 0.f;
    #pragma unroll
    for (int j = 0; j < 16; j++) s = fmaf(fmaxf(h[j], 0.f), sw[q * 16 + j], s);

    s += __shfl_xor_sync(0xffffffffu, s, 1, 32);
    s += __shfl_xor_sync(0xffffffffu, s, 2, 32);

    if (valid && q == 0) out[row] = s + __ldg(bv);
}

// ---------------------------------------------------------------------------
static inline int imin(int a, int b) { return a < b ? a : b; }

extern "C" void kernel_launch(void* const* d_in, const int* in_sizes, int n_in,
                              void* d_out, int out_size)
{
    const float* x_state   = (const float*)d_in[0];
    const float* x_task    = (const float*)d_in[1];
    const float* x_actor   = (const float*)d_in[2];
    const float* edge_attr = (const float*)d_in[3];
    const float* We  = (const float*)d_in[4];
    const float* be  = (const float*)d_in[5];
    const float* W1a = (const float*)d_in[6];
    const float* b1a = (const float*)d_in[7];
    const float* W1b = (const float*)d_in[8];
    const float* b1b = (const float*)d_in[9];
    const float* W2a = (const float*)d_in[10];
    const float* b2a = (const float*)d_in[11];
    const float* W2b = (const float*)d_in[12];
    const float* b2b = (const float*)d_in[13];
    const int* src_st = (const int*)d_in[14];
    const int* dst_st = (const int*)d_in[15];
    const int* src_ta = (const int*)d_in[16];
    const int* dst_ta = (const int*)d_in[17];

    const int n_task  = in_sizes[1] / F64;
    const int n_actor = in_sizes[2] / F64;
    const int E_st = in_sizes[14];
    const int E_ta = in_sizes[16];

    float *p_h_task, *p_x1, *p_h2;
    cudaGetSymbolAddress((void**)&p_h_task, g_h_task);
    cudaGetSymbolAddress((void**)&p_x1,     g_x1);
    cudaGetSymbolAddress((void**)&p_h2,     g_h2);

    // 1) residual init
    init_kernel<<<1024, 256>>>(x_task, x_actor, n_task, n_actor);

    // 2) GINEConv message + scatter
    {
        int blocks = imin((E_st * 16 + 255) / 256, 148 * 48);
        edge_gine_kernel<<<blocks, 256>>>(x_state, edge_attr, We, be,
                                          src_st, dst_st, E_st);
    }

    // 3) task MLP (fused) -> x1
    mlp2_kernel<<<(n_task * 4 + 255) / 256, 256>>>(p_h_task, W1a, b1a, W1b, b1b,
                                                   p_x1, n_task);

    // 4) GINConv gather + scatter
    {
        int blocks = imin((E_ta * 16 + 255) / 256, 148 * 48);
        edge_gin_kernel<<<blocks, 256>>>(src_ta, dst_ta, E_ta);
    }

    // 5) actor MLP + head -> logits
    mlp_head_kernel<<<(n_actor * 4 + 255) / 256, 256>>>(p_h2, W2a, b2a, W2b, b2b,
                                                        (float*)d_out, n_actor);
}